// round 1
// baseline (speedup 1.0000x reference)
#include <cuda_runtime.h>
#include <math.h>

// Problem constants
#define B_SZ   2
#define S_LEN  2048
#define D_EMB  1024
#define NHEAD  16
#define HDIM   64
#define M_TOT  (B_SZ * S_LEN)   // 4096

// Scratch (device globals: allocation-free per harness rules)
__device__ float g_q[M_TOT * D_EMB];
__device__ float g_k[M_TOT * D_EMB];
__device__ float g_v[M_TOT * D_EMB];
__device__ float g_a[M_TOT * D_EMB];

// ---------------------------------------------------------------------------
// SGEMM: C[M,N] = A[M,K] @ B[K,N] + bias[N]
// 128x128 tile, BK=8, 8x8 per thread, 256 threads.
// ---------------------------------------------------------------------------
__global__ void __launch_bounds__(256) sgemm_bias(
    const float* __restrict__ A, const float* __restrict__ B,
    const float* __restrict__ bias, float* __restrict__ C,
    int M, int N, int K)
{
    const int BM = 128, BN = 128, BK = 8, TM = 8, TN = 8;
    __shared__ float As[BK][BM];
    __shared__ float Bs[BK][BN];

    int tid = threadIdx.x;
    int bx = blockIdx.x;   // N tiles
    int by = blockIdx.y;   // M tiles

    int aRow = tid >> 1;               // 0..127
    int aCol = (tid & 1) << 2;         // 0 or 4
    int bRow = tid >> 5;               // 0..7
    int bCol = (tid & 31) << 2;        // 0..124

    int tRow = (tid >> 4) << 3;        // 0..120
    int tCol = (tid & 15) << 3;        // 0..120

    const float* Ap = A + (size_t)(by * BM + aRow) * K + aCol;
    const float* Bp = B + (size_t)bRow * N + bx * BN + bCol;

    float acc[TM][TN];
    #pragma unroll
    for (int i = 0; i < TM; i++)
        #pragma unroll
        for (int j = 0; j < TN; j++) acc[i][j] = 0.0f;

    for (int k0 = 0; k0 < K; k0 += BK) {
        float4 av = *(const float4*)(Ap + k0);
        float4 bv = *(const float4*)(Bp + (size_t)k0 * N);
        As[aCol + 0][aRow] = av.x;
        As[aCol + 1][aRow] = av.y;
        As[aCol + 2][aRow] = av.z;
        As[aCol + 3][aRow] = av.w;
        *(float4*)&Bs[bRow][bCol] = bv;
        __syncthreads();

        #pragma unroll
        for (int k = 0; k < BK; k++) {
            float ar[TM], br[TN];
            #pragma unroll
            for (int i = 0; i < TM; i++) ar[i] = As[k][tRow + i];
            #pragma unroll
            for (int j = 0; j < TN; j++) br[j] = Bs[k][tCol + j];
            #pragma unroll
            for (int i = 0; i < TM; i++)
                #pragma unroll
                for (int j = 0; j < TN; j++)
                    acc[i][j] = fmaf(ar[i], br[j], acc[i][j]);
        }
        __syncthreads();
    }

    int row0 = by * BM + tRow;
    int col0 = bx * BN + tCol;
    #pragma unroll
    for (int i = 0; i < TM; i++) {
        #pragma unroll
        for (int j = 0; j < TN; j++) acc[i][j] += bias[col0 + j];
        *(float4*)&C[(size_t)(row0 + i) * N + col0] =
            make_float4(acc[i][0], acc[i][1], acc[i][2], acc[i][3]);
        *(float4*)&C[(size_t)(row0 + i) * N + col0 + 4] =
            make_float4(acc[i][4], acc[i][5], acc[i][6], acc[i][7]);
    }
}

// ---------------------------------------------------------------------------
// Flash attention (fp32). One CTA per (b, h, 64-row q-tile).
// 256 threads: ty=tid/16 (row group of 4), tx=tid%16 (col group of 4).
// Kst holds the K tile TRANSPOSED (d-major) so QK^T reads are float4
// conflict-free; Kst is reused as the P tile (64x64) between syncs.
// ---------------------------------------------------------------------------
__global__ void __launch_bounds__(256) attn_kernel(
    const float* __restrict__ Q, const float* __restrict__ Kg,
    const float* __restrict__ Vg, float* __restrict__ Og)
{
    __shared__ float Qs[64][64];
    __shared__ float Kst[64][64];   // [d][kv] during QK; [q][kv] as P tile
    __shared__ float Vs[64][64];

    const int b  = blockIdx.z;
    const int h  = blockIdx.y;
    const int q0 = blockIdx.x * 64;

    const int tid = threadIdx.x;
    const int ty = tid >> 4, tx = tid & 15;
    const int r0 = ty << 2, c0 = tx << 2;

    // Load Q tile: 64 rows x 64 cols (16 float4 per row), 4 float4 / thread
    {
        int row = tid >> 2;
        int v0  = tid & 3;
        const float* src = Q + (size_t)(b * S_LEN + q0 + row) * D_EMB + h * HDIM;
        #pragma unroll
        for (int i = 0; i < 4; i++) {
            int v = v0 + (i << 2);
            *(float4*)&Qs[row][v << 2] = *(const float4*)(src + (v << 2));
        }
    }

    float acc[4][4];
    float m_i[4], l_i[4];
    #pragma unroll
    for (int i = 0; i < 4; i++) {
        m_i[i] = -1e30f; l_i[i] = 0.0f;
        #pragma unroll
        for (int j = 0; j < 4; j++) acc[i][j] = 0.0f;
    }

    for (int kt = 0; kt < S_LEN; kt += 64) {
        __syncthreads();  // guard: previous P/V reads done (and Q load on iter 0... see below)
        // Load K tile transposed + V tile
        {
            int row = tid >> 2;
            int v0  = tid & 3;
            const float* ksrc = Kg + (size_t)(b * S_LEN + kt + row) * D_EMB + h * HDIM;
            const float* vsrc = Vg + (size_t)(b * S_LEN + kt + row) * D_EMB + h * HDIM;
            #pragma unroll
            for (int i = 0; i < 4; i++) {
                int v = v0 + (i << 2);
                float4 kv = *(const float4*)(ksrc + (v << 2));
                Kst[(v << 2) + 0][row] = kv.x;
                Kst[(v << 2) + 1][row] = kv.y;
                Kst[(v << 2) + 2][row] = kv.z;
                Kst[(v << 2) + 3][row] = kv.w;
                *(float4*)&Vs[row][v << 2] = *(const float4*)(vsrc + (v << 2));
            }
        }
        __syncthreads();

        // S = (Q K^T) * 1/sqrt(64)
        float s[4][4];
        #pragma unroll
        for (int i = 0; i < 4; i++)
            #pragma unroll
            for (int j = 0; j < 4; j++) s[i][j] = 0.0f;

        #pragma unroll 4
        for (int d = 0; d < 64; d++) {
            float qv[4];
            #pragma unroll
            for (int i = 0; i < 4; i++) qv[i] = Qs[r0 + i][d];
            float4 kv = *(const float4*)&Kst[d][c0];
            #pragma unroll
            for (int i = 0; i < 4; i++) {
                s[i][0] = fmaf(qv[i], kv.x, s[i][0]);
                s[i][1] = fmaf(qv[i], kv.y, s[i][1]);
                s[i][2] = fmaf(qv[i], kv.z, s[i][2]);
                s[i][3] = fmaf(qv[i], kv.w, s[i][3]);
            }
        }

        // Online softmax update
        float p[4][4];
        #pragma unroll
        for (int i = 0; i < 4; i++) {
            float rmax = -1e30f;
            #pragma unroll
            for (int j = 0; j < 4; j++) {
                s[i][j] *= 0.125f;
                rmax = fmaxf(rmax, s[i][j]);
            }
            // reduce max across the 16 lanes sharing this row group
            #pragma unroll
            for (int off = 8; off >= 1; off >>= 1)
                rmax = fmaxf(rmax, __shfl_xor_sync(0xffffffffu, rmax, off));

            float mnew = fmaxf(m_i[i], rmax);
            float fac  = __expf(m_i[i] - mnew);
            float rsum = 0.0f;
            #pragma unroll
            for (int j = 0; j < 4; j++) {
                p[i][j] = __expf(s[i][j] - mnew);
                rsum += p[i][j];
            }
            #pragma unroll
            for (int off = 8; off >= 1; off >>= 1)
                rsum += __shfl_xor_sync(0xffffffffu, rsum, off);

            l_i[i] = l_i[i] * fac + rsum;
            m_i[i] = mnew;
            #pragma unroll
            for (int j = 0; j < 4; j++) acc[i][j] *= fac;
        }

        __syncthreads();  // everyone done reading Kst (QK phase)
        // Write P into the Kst buffer: P[q][kv]
        #pragma unroll
        for (int i = 0; i < 4; i++)
            *(float4*)&Kst[r0 + i][c0] = make_float4(p[i][0], p[i][1], p[i][2], p[i][3]);
        __syncthreads();

        // O += P @ V
        #pragma unroll 4
        for (int k = 0; k < 64; k++) {
            float pv[4];
            #pragma unroll
            for (int i = 0; i < 4; i++) pv[i] = Kst[r0 + i][k];
            float4 vv = *(const float4*)&Vs[k][c0];
            #pragma unroll
            for (int i = 0; i < 4; i++) {
                acc[i][0] = fmaf(pv[i], vv.x, acc[i][0]);
                acc[i][1] = fmaf(pv[i], vv.y, acc[i][1]);
                acc[i][2] = fmaf(pv[i], vv.z, acc[i][2]);
                acc[i][3] = fmaf(pv[i], vv.w, acc[i][3]);
            }
        }
    }

    // Epilogue: normalize and store to [b, q, h, d] layout
    #pragma unroll
    for (int i = 0; i < 4; i++) {
        float inv = 1.0f / l_i[i];
        float4 o = make_float4(acc[i][0] * inv, acc[i][1] * inv,
                               acc[i][2] * inv, acc[i][3] * inv);
        *(float4*)&Og[(size_t)(b * S_LEN + q0 + r0 + i) * D_EMB + h * HDIM + c0] = o;
    }
}

// ---------------------------------------------------------------------------
// Launcher
// ---------------------------------------------------------------------------
extern "C" void kernel_launch(void* const* d_in, const int* in_sizes, int n_in,
                              void* d_out, int out_size)
{
    const float* x  = (const float*)d_in[0];
    const float* wq = (const float*)d_in[1];
    const float* bq = (const float*)d_in[2];
    const float* wk = (const float*)d_in[3];
    const float* bk = (const float*)d_in[4];
    const float* wv = (const float*)d_in[5];
    const float* bv = (const float*)d_in[6];
    const float* wo = (const float*)d_in[7];
    const float* bo = (const float*)d_in[8];
    float* out = (float*)d_out;

    float *q, *k, *v, *a;
    cudaGetSymbolAddress((void**)&q, g_q);
    cudaGetSymbolAddress((void**)&k, g_k);
    cudaGetSymbolAddress((void**)&v, g_v);
    cudaGetSymbolAddress((void**)&a, g_a);

    dim3 ggrid(D_EMB / 128, M_TOT / 128);   // (8, 32)
    sgemm_bias<<<ggrid, 256>>>(x, wq, bq, q, M_TOT, D_EMB, D_EMB);
    sgemm_bias<<<ggrid, 256>>>(x, wk, bk, k, M_TOT, D_EMB, D_EMB);
    sgemm_bias<<<ggrid, 256>>>(x, wv, bv, v, M_TOT, D_EMB, D_EMB);

    dim3 agrid(S_LEN / 64, NHEAD, B_SZ);    // (32, 16, 2)
    attn_kernel<<<agrid, 256>>>(q, k, v, a);

    sgemm_bias<<<ggrid, 256>>>(a, wo, bo, out, M_TOT, D_EMB, D_EMB);
}

// round 3
// speedup vs baseline: 3.2673x; 3.2673x over previous
#include <cuda_runtime.h>
#include <cuda_bf16.h>
#include <cstdint>
#include <math.h>

// Problem constants
#define B_SZ   2
#define S_LEN  2048
#define D_EMB  1024
#define NHEAD  16
#define HDIM   64
#define M_TOT  (B_SZ * S_LEN)   // 4096

// ---------------------------------------------------------------------------
// Device-global scratch (allocation-free per harness rules)
// ---------------------------------------------------------------------------
__device__ __nv_bfloat16 g_xhi[M_TOT * D_EMB];
__device__ __nv_bfloat16 g_xlo[M_TOT * D_EMB];
__device__ __nv_bfloat16 g_qhi[M_TOT * D_EMB];
__device__ __nv_bfloat16 g_qlo[M_TOT * D_EMB];
__device__ __nv_bfloat16 g_khi[M_TOT * D_EMB];
__device__ __nv_bfloat16 g_klo[M_TOT * D_EMB];
__device__ __nv_bfloat16 g_vhi[M_TOT * D_EMB];
__device__ __nv_bfloat16 g_vlo[M_TOT * D_EMB];
__device__ __nv_bfloat16 g_ahi[M_TOT * D_EMB];
__device__ __nv_bfloat16 g_alo[M_TOT * D_EMB];
__device__ __nv_bfloat16 g_wthi[D_EMB * D_EMB];   // W^T [N][K], reused per GEMM
__device__ __nv_bfloat16 g_wtlo[D_EMB * D_EMB];

// ---------------------------------------------------------------------------
// PTX helpers (all baseline-target instructions: sm_80-era, valid on compute_103)
// ---------------------------------------------------------------------------
__device__ __forceinline__ uint32_t smem_u32(const void* p) {
    uint32_t a;
    asm("{ .reg .u64 t; cvta.to.shared.u64 t, %1; cvt.u32.u64 %0, t; }" : "=r"(a) : "l"(p));
    return a;
}
__device__ __forceinline__ void cpasync16(uint32_t saddr, const void* g) {
    asm volatile("cp.async.cg.shared.global [%0], [%1], 16;" :: "r"(saddr), "l"(g));
}
#define CP_COMMIT() asm volatile("cp.async.commit_group;" ::: "memory")
#define CP_WAIT(n)  asm volatile("cp.async.wait_group %0;" :: "n"(n) : "memory")

__device__ __forceinline__ void ldsm4(uint32_t* r, uint32_t addr) {
    asm volatile("ldmatrix.sync.aligned.m8n8.x4.shared.b16 {%0,%1,%2,%3}, [%4];"
        : "=r"(r[0]), "=r"(r[1]), "=r"(r[2]), "=r"(r[3]) : "r"(addr));
}
__device__ __forceinline__ void ldsm4t(uint32_t* r, uint32_t addr) {
    asm volatile("ldmatrix.sync.aligned.m8n8.x4.trans.shared.b16 {%0,%1,%2,%3}, [%4];"
        : "=r"(r[0]), "=r"(r[1]), "=r"(r[2]), "=r"(r[3]) : "r"(addr));
}
// D = A*B + D : m16n8k16, bf16 in, f32 accum
__device__ __forceinline__ void mma16816(float* c, const uint32_t* a, const uint32_t* b) {
    asm volatile("mma.sync.aligned.m16n8k16.row.col.f32.bf16.bf16.f32 "
        "{%0,%1,%2,%3},{%4,%5,%6,%7},{%8,%9},{%0,%1,%2,%3};"
        : "+f"(c[0]), "+f"(c[1]), "+f"(c[2]), "+f"(c[3])
        : "r"(a[0]), "r"(a[1]), "r"(a[2]), "r"(a[3]), "r"(b[0]), "r"(b[1]));
}

// split fp32 -> bf16 hi + bf16 lo, packed pairs
__device__ __forceinline__ void split_pack(float x, float y, uint32_t& hi, uint32_t& lo) {
    __nv_bfloat162 h, l;
    h.x = __float2bfloat16_rn(x);
    h.y = __float2bfloat16_rn(y);
    l.x = __float2bfloat16_rn(x - __bfloat162float(h.x));
    l.y = __float2bfloat16_rn(y - __bfloat162float(h.y));
    hi = *reinterpret_cast<uint32_t*>(&h);
    lo = *reinterpret_cast<uint32_t*>(&l);
}

// ---------------------------------------------------------------------------
// Prep kernels
// ---------------------------------------------------------------------------
__global__ void __launch_bounds__(256) split_f32(
    const float* __restrict__ in, __nv_bfloat16* __restrict__ hi,
    __nv_bfloat16* __restrict__ lo, int n)
{
    int i = blockIdx.x * blockDim.x + threadIdx.x;
    if (i < n) {
        float v = in[i];
        __nv_bfloat16 h = __float2bfloat16_rn(v);
        hi[i] = h;
        lo[i] = __float2bfloat16_rn(v - __bfloat162float(h));
    }
}

// W[K][N] row-major -> Thi/Tlo [N][K]
__global__ void __launch_bounds__(256) split_w_t(
    const float* __restrict__ W, __nv_bfloat16* __restrict__ Thi,
    __nv_bfloat16* __restrict__ Tlo)
{
    __shared__ float t[32][33];
    int n0 = blockIdx.x * 32, k0 = blockIdx.y * 32;
    int tx = threadIdx.x, ty = threadIdx.y;
    #pragma unroll
    for (int r = ty; r < 32; r += 8)
        t[r][tx] = W[(size_t)(k0 + r) * D_EMB + n0 + tx];
    __syncthreads();
    #pragma unroll
    for (int r = ty; r < 32; r += 8) {
        float v = t[tx][r];   // W[k0+tx][n0+r]
        __nv_bfloat16 h = __float2bfloat16_rn(v);
        size_t o = (size_t)(n0 + r) * D_EMB + k0 + tx;
        Thi[o] = h;
        Tlo[o] = __float2bfloat16_rn(v - __bfloat162float(h));
    }
}

// ---------------------------------------------------------------------------
// HMMA split-bf16 GEMM: C[4096,1024] = (Ahi+Alo)[M,K] @ (Bhi+Blo)[N,K]^T + bias
// Tile 128x128, BK=32, 8 warps (4x2), double-buffered cp.async.
// smem per stage: Ahi 8K | Alo 8K | Bhi 8K | Blo 8K = 32KB; 2 stages = 64KB
// 64B rows (32 bf16), swizzle chunk' = chunk ^ ((row>>1)&3)
// ---------------------------------------------------------------------------
#define NC_G 32

template<bool SPLIT_OUT>
__global__ void __launch_bounds__(256) gemm_mma(
    const __nv_bfloat16* __restrict__ Ahi, const __nv_bfloat16* __restrict__ Alo,
    const __nv_bfloat16* __restrict__ Bhi, const __nv_bfloat16* __restrict__ Blo,
    const float* __restrict__ bias, float* __restrict__ Cf,
    __nv_bfloat16* __restrict__ Chi, __nv_bfloat16* __restrict__ Clo)
{
    extern __shared__ __align__(1024) char smg[];
    const uint32_t sb = smem_u32(smg);
    const int tid = threadIdx.x, lane = tid & 31, wid = tid >> 5;
    const int wm = wid & 3, wn = wid >> 2;
    const int m0 = blockIdx.y * 128, n0 = blockIdx.x * 128;

    float acc[2][8][4];
    #pragma unroll
    for (int i = 0; i < 2; i++)
        #pragma unroll
        for (int j = 0; j < 8; j++)
            #pragma unroll
            for (int q = 0; q < 4; q++) acc[i][j][q] = 0.0f;

    auto issue = [&](int kc) {
        uint32_t base = sb + (kc & 1) * 32768;
        const int k0 = kc * 32;
        #pragma unroll
        for (int r = 0; r < 2; r++) {
            int idx = tid + r * 256;             // 0..511
            int row = idx >> 2, c = idx & 3;
            uint32_t sw = (uint32_t)(row * 64 + ((c ^ ((row >> 1) & 3)) << 4));
            size_t ga = (size_t)(m0 + row) * D_EMB + k0 + c * 8;
            size_t gb = (size_t)(n0 + row) * D_EMB + k0 + c * 8;
            cpasync16(base + sw,          Ahi + ga);
            cpasync16(base + 8192 + sw,   Alo + ga);
            cpasync16(base + 16384 + sw,  Bhi + gb);
            cpasync16(base + 24576 + sw,  Blo + gb);
        }
        CP_COMMIT();
    };

    issue(0);
    for (int kc = 0; kc < NC_G; kc++) {
        if (kc + 1 < NC_G) { issue(kc + 1); CP_WAIT(1); }
        else               { CP_WAIT(0); }
        __syncthreads();

        uint32_t aB = sb + (kc & 1) * 32768;
        uint32_t bB = aB + 16384;
        #pragma unroll
        for (int k = 0; k < 2; k++) {
            uint32_t ah[2][4], al[2][4];
            #pragma unroll
            for (int mt = 0; mt < 2; mt++) {
                int row = wm * 32 + mt * 16 + (lane & 15);
                int ch = k * 2 + (lane >> 4);
                uint32_t off = (uint32_t)(row * 64 + ((ch ^ ((row >> 1) & 3)) << 4));
                ldsm4(ah[mt], aB + off);
                ldsm4(al[mt], aB + 8192 + off);
            }
            #pragma unroll
            for (int np = 0; np < 4; np++) {
                int row = wn * 64 + np * 16 + ((lane >> 4) << 3) + (lane & 7);
                int ch = k * 2 + ((lane >> 3) & 1);
                uint32_t off = (uint32_t)(row * 64 + ((ch ^ ((row >> 1) & 3)) << 4));
                uint32_t bh[4], bl[4];
                ldsm4(bh, bB + off);
                ldsm4(bl, bB + 8192 + off);
                #pragma unroll
                for (int nt = 0; nt < 2; nt++) {
                    #pragma unroll
                    for (int mt = 0; mt < 2; mt++) {
                        float* cc = acc[mt][np * 2 + nt];
                        mma16816(cc, ah[mt], bh + nt * 2);
                        mma16816(cc, ah[mt], bl + nt * 2);
                        mma16816(cc, al[mt], bh + nt * 2);
                    }
                }
            }
        }
        __syncthreads();
    }

    // Epilogue
    #pragma unroll
    for (int mt = 0; mt < 2; mt++) {
        int r_ = m0 + wm * 32 + mt * 16 + (lane >> 2);
        #pragma unroll
        for (int nt = 0; nt < 8; nt++) {
            int col = n0 + wn * 64 + nt * 8 + 2 * (lane & 3);
            float b0 = bias[col], b1 = bias[col + 1];
            float v00 = acc[mt][nt][0] + b0, v01 = acc[mt][nt][1] + b1;
            float v10 = acc[mt][nt][2] + b0, v11 = acc[mt][nt][3] + b1;
            if (SPLIT_OUT) {
                uint32_t h0, l0, h1, l1;
                split_pack(v00, v01, h0, l0);
                split_pack(v10, v11, h1, l1);
                *(uint32_t*)(Chi + (size_t)r_ * D_EMB + col)       = h0;
                *(uint32_t*)(Clo + (size_t)r_ * D_EMB + col)       = l0;
                *(uint32_t*)(Chi + (size_t)(r_ + 8) * D_EMB + col) = h1;
                *(uint32_t*)(Clo + (size_t)(r_ + 8) * D_EMB + col) = l1;
            } else {
                *(float2*)(Cf + (size_t)r_ * D_EMB + col)       = make_float2(v00, v01);
                *(float2*)(Cf + (size_t)(r_ + 8) * D_EMB + col) = make_float2(v10, v11);
            }
        }
    }
}

// ---------------------------------------------------------------------------
// HMMA flash attention. CTA = (b, h, 128 q-rows); 8 warps, warp owns 16 rows.
// kv chunk = 64 rows, double-buffered cp.async. 128B smem rows (64 bf16),
// swizzle chunk' = chunk ^ (row&7).
// smem: Qhi 16K | Qlo 16K | 2 stages x (Khi 8K | Klo 8K | Vhi 8K | Vlo 8K)
// ---------------------------------------------------------------------------
#define ANC (S_LEN / 64)   // 32

__global__ void __launch_bounds__(256) attn_mma(
    const __nv_bfloat16* __restrict__ Qhi, const __nv_bfloat16* __restrict__ Qlo,
    const __nv_bfloat16* __restrict__ Khi, const __nv_bfloat16* __restrict__ Klo,
    const __nv_bfloat16* __restrict__ Vhi, const __nv_bfloat16* __restrict__ Vlo,
    __nv_bfloat16* __restrict__ Ohi, __nv_bfloat16* __restrict__ Olo)
{
    extern __shared__ __align__(1024) char sma[];
    const uint32_t sb = smem_u32(sma);
    const int tid = threadIdx.x, lane = tid & 31, wid = tid >> 5;
    const int b = blockIdx.z, h = blockIdx.y, q0 = blockIdx.x * 128;
    const size_t rowbase = (size_t)b * S_LEN;
    const int colbase = h * HDIM;

    // issue Q (group with KV0)
    {
        #pragma unroll
        for (int r = 0; r < 4; r++) {
            int idx = tid + r * 256;       // 0..1023
            int row = idx >> 3, c = idx & 7;
            uint32_t sw = (uint32_t)(row * 128 + ((c ^ (row & 7)) << 4));
            size_t g = (rowbase + q0 + row) * D_EMB + colbase + c * 8;
            cpasync16(sb + sw,         Qhi + g);
            cpasync16(sb + 16384 + sw, Qlo + g);
        }
    }
    auto issueKV = [&](int kc) {
        uint32_t base = sb + 32768 + (kc & 1) * 32768;
        #pragma unroll
        for (int r = 0; r < 2; r++) {
            int idx = tid + r * 256;       // 0..511
            int row = idx >> 3, c = idx & 7;
            uint32_t sw = (uint32_t)(row * 128 + ((c ^ (row & 7)) << 4));
            size_t g = (rowbase + kc * 64 + row) * D_EMB + colbase + c * 8;
            cpasync16(base + sw,          Khi + g);
            cpasync16(base + 8192 + sw,   Klo + g);
            cpasync16(base + 16384 + sw,  Vhi + g);
            cpasync16(base + 24576 + sw,  Vlo + g);
        }
    };
    issueKV(0);
    CP_COMMIT();   // group 0 = Q + KV0

    uint32_t qh[4][4], ql[4][4];
    float o[8][4];
    #pragma unroll
    for (int j = 0; j < 8; j++)
        #pragma unroll
        for (int q = 0; q < 4; q++) o[j][q] = 0.0f;
    float m1 = -1e30f, m2 = -1e30f, l1 = 0.0f, l2 = 0.0f;

    for (int kc = 0; kc < ANC; kc++) {
        if (kc + 1 < ANC) { issueKV(kc + 1); CP_COMMIT(); CP_WAIT(1); }
        else              { CP_WAIT(0); }
        __syncthreads();

        if (kc == 0) {
            // Load Q fragments once (registers persist all chunks)
            #pragma unroll
            for (int k = 0; k < 4; k++) {
                int row = wid * 16 + (lane & 15);
                int ch = k * 2 + (lane >> 4);
                uint32_t off = (uint32_t)(row * 128 + ((ch ^ (row & 7)) << 4));
                ldsm4(qh[k], sb + off);
                ldsm4(ql[k], sb + 16384 + off);
            }
        }

        uint32_t kB = sb + 32768 + (kc & 1) * 32768;
        // ---- S = Q K^T ----
        float s[8][4];
        #pragma unroll
        for (int j = 0; j < 8; j++)
            #pragma unroll
            for (int q = 0; q < 4; q++) s[j][q] = 0.0f;

        #pragma unroll
        for (int k = 0; k < 4; k++) {
            #pragma unroll
            for (int np = 0; np < 4; np++) {
                int row = np * 16 + ((lane >> 4) << 3) + (lane & 7);
                int ch = k * 2 + ((lane >> 3) & 1);
                uint32_t off = (uint32_t)(row * 128 + ((ch ^ (row & 7)) << 4));
                uint32_t bh[4], bl[4];
                ldsm4(bh, kB + off);
                ldsm4(bl, kB + 8192 + off);
                #pragma unroll
                for (int nt = 0; nt < 2; nt++) {
                    float* cc = s[np * 2 + nt];
                    mma16816(cc, qh[k], bh + nt * 2);
                    mma16816(cc, qh[k], bl + nt * 2);
                    mma16816(cc, ql[k], bh + nt * 2);
                }
            }
        }

        // ---- online softmax (rows r=lane>>2 and r+8) ----
        float rm1 = -1e30f, rm2 = -1e30f;
        #pragma unroll
        for (int j = 0; j < 8; j++) {
            #pragma unroll
            for (int q = 0; q < 4; q++) s[j][q] *= 0.125f;
            rm1 = fmaxf(rm1, fmaxf(s[j][0], s[j][1]));
            rm2 = fmaxf(rm2, fmaxf(s[j][2], s[j][3]));
        }
        rm1 = fmaxf(rm1, __shfl_xor_sync(0xffffffffu, rm1, 1));
        rm1 = fmaxf(rm1, __shfl_xor_sync(0xffffffffu, rm1, 2));
        rm2 = fmaxf(rm2, __shfl_xor_sync(0xffffffffu, rm2, 1));
        rm2 = fmaxf(rm2, __shfl_xor_sync(0xffffffffu, rm2, 2));

        float mn1 = fmaxf(m1, rm1), mn2 = fmaxf(m2, rm2);
        float f1 = __expf(m1 - mn1), f2 = __expf(m2 - mn2);
        float rs1 = 0.0f, rs2 = 0.0f;
        #pragma unroll
        for (int j = 0; j < 8; j++) {
            s[j][0] = __expf(s[j][0] - mn1);
            s[j][1] = __expf(s[j][1] - mn1);
            s[j][2] = __expf(s[j][2] - mn2);
            s[j][3] = __expf(s[j][3] - mn2);
            rs1 += s[j][0] + s[j][1];
            rs2 += s[j][2] + s[j][3];
        }
        rs1 += __shfl_xor_sync(0xffffffffu, rs1, 1);
        rs1 += __shfl_xor_sync(0xffffffffu, rs1, 2);
        rs2 += __shfl_xor_sync(0xffffffffu, rs2, 1);
        rs2 += __shfl_xor_sync(0xffffffffu, rs2, 2);
        l1 = l1 * f1 + rs1;
        l2 = l2 * f2 + rs2;
        m1 = mn1; m2 = mn2;
        #pragma unroll
        for (int j = 0; j < 8; j++) {
            o[j][0] *= f1; o[j][1] *= f1;
            o[j][2] *= f2; o[j][3] *= f2;
        }

        // ---- O += P V : repack P (C-frag -> A-frag) in registers ----
        uint32_t vB = kB + 16384;
        #pragma unroll
        for (int kk = 0; kk < 4; kk++) {
            uint32_t ph[4], pl[4];
            split_pack(s[2 * kk][0],     s[2 * kk][1],     ph[0], pl[0]);
            split_pack(s[2 * kk][2],     s[2 * kk][3],     ph[1], pl[1]);
            split_pack(s[2 * kk + 1][0], s[2 * kk + 1][1], ph[2], pl[2]);
            split_pack(s[2 * kk + 1][2], s[2 * kk + 1][3], ph[3], pl[3]);
            #pragma unroll
            for (int dp = 0; dp < 4; dp++) {
                int row = kk * 16 + ((lane >> 3) & 1) * 8 + (lane & 7);
                int ch = dp * 2 + (lane >> 4);
                uint32_t off = (uint32_t)(row * 128 + ((ch ^ (row & 7)) << 4));
                uint32_t vh[4], vl[4];
                ldsm4t(vh, vB + off);
                ldsm4t(vl, vB + 8192 + off);
                #pragma unroll
                for (int nt = 0; nt < 2; nt++) {
                    float* oo = o[dp * 2 + nt];
                    mma16816(oo, ph, vh + nt * 2);
                    mma16816(oo, ph, vl + nt * 2);
                    mma16816(oo, pl, vh + nt * 2);
                }
            }
        }
        __syncthreads();
    }

    // ---- epilogue: normalize, split to bf16 hi/lo ----
    float i1 = 1.0f / l1, i2 = 1.0f / l2;
    int r_ = q0 + wid * 16 + (lane >> 2);
    #pragma unroll
    for (int nt = 0; nt < 8; nt++) {
        int col = colbase + nt * 8 + 2 * (lane & 3);
        uint32_t h0, l0g, h1, l1g;
        split_pack(o[nt][0] * i1, o[nt][1] * i1, h0, l0g);
        split_pack(o[nt][2] * i2, o[nt][3] * i2, h1, l1g);
        size_t base0 = (rowbase + r_) * D_EMB + col;
        size_t base1 = (rowbase + r_ + 8) * D_EMB + col;
        *(uint32_t*)(Ohi + base0) = h0;
        *(uint32_t*)(Olo + base0) = l0g;
        *(uint32_t*)(Ohi + base1) = h1;
        *(uint32_t*)(Olo + base1) = l1g;
    }
}

// ---------------------------------------------------------------------------
// Launcher
// ---------------------------------------------------------------------------
extern "C" void kernel_launch(void* const* d_in, const int* in_sizes, int n_in,
                              void* d_out, int out_size)
{
    const float* x  = (const float*)d_in[0];
    const float* wq = (const float*)d_in[1];
    const float* bq = (const float*)d_in[2];
    const float* wk = (const float*)d_in[3];
    const float* bk = (const float*)d_in[4];
    const float* wv = (const float*)d_in[5];
    const float* bv = (const float*)d_in[6];
    const float* wo = (const float*)d_in[7];
    const float* bo = (const float*)d_in[8];
    float* out = (float*)d_out;

    __nv_bfloat16 *xhi, *xlo, *qhi, *qlo, *khi, *klo, *vhi, *vlo, *ahi, *alo, *wthi, *wtlo;
    cudaGetSymbolAddress((void**)&xhi, g_xhi);
    cudaGetSymbolAddress((void**)&xlo, g_xlo);
    cudaGetSymbolAddress((void**)&qhi, g_qhi);
    cudaGetSymbolAddress((void**)&qlo, g_qlo);
    cudaGetSymbolAddress((void**)&khi, g_khi);
    cudaGetSymbolAddress((void**)&klo, g_klo);
    cudaGetSymbolAddress((void**)&vhi, g_vhi);
    cudaGetSymbolAddress((void**)&vlo, g_vlo);
    cudaGetSymbolAddress((void**)&ahi, g_ahi);
    cudaGetSymbolAddress((void**)&alo, g_alo);
    cudaGetSymbolAddress((void**)&wthi, g_wthi);
    cudaGetSymbolAddress((void**)&wtlo, g_wtlo);

    cudaFuncSetAttribute(gemm_mma<true>,  cudaFuncAttributeMaxDynamicSharedMemorySize, 65536);
    cudaFuncSetAttribute(gemm_mma<false>, cudaFuncAttributeMaxDynamicSharedMemorySize, 65536);
    cudaFuncSetAttribute(attn_mma,        cudaFuncAttributeMaxDynamicSharedMemorySize, 98304);

    const int NELEM = M_TOT * D_EMB;
    dim3 wgrid(D_EMB / 32, D_EMB / 32);
    dim3 wblk(32, 8);
    dim3 ggrid(D_EMB / 128, M_TOT / 128);   // (8, 32)

    split_f32<<<(NELEM + 255) / 256, 256>>>(x, xhi, xlo, NELEM);

    split_w_t<<<wgrid, wblk>>>(wq, wthi, wtlo);
    gemm_mma<true><<<ggrid, 256, 65536>>>(xhi, xlo, wthi, wtlo, bq, nullptr, qhi, qlo);
    split_w_t<<<wgrid, wblk>>>(wk, wthi, wtlo);
    gemm_mma<true><<<ggrid, 256, 65536>>>(xhi, xlo, wthi, wtlo, bk, nullptr, khi, klo);
    split_w_t<<<wgrid, wblk>>>(wv, wthi, wtlo);
    gemm_mma<true><<<ggrid, 256, 65536>>>(xhi, xlo, wthi, wtlo, bv, nullptr, vhi, vlo);

    dim3 agrid(S_LEN / 128, NHEAD, B_SZ);    // (16, 16, 2)
    attn_mma<<<agrid, 256, 98304>>>(qhi, qlo, khi, klo, vhi, vlo, ahi, alo);

    split_w_t<<<wgrid, wblk>>>(wo, wthi, wtlo);
    gemm_mma<false><<<ggrid, 256, 65536>>>(ahi, alo, wthi, wtlo, bo, out, nullptr, nullptr);
}